// round 6
// baseline (speedup 1.0000x reference)
#include <cuda_runtime.h>
#include <cuda_bf16.h>

#define BB 4
#define NN 256
#define HH 256
#define WW 256
#define HW 65536   // HH*WW

// Scratch (device globals — no allocations allowed)
__device__ int      g_cidx[BB * NN];    // flat center index within HxW for each (b,n)
__device__ float    g_scale[BB * NN];   // 0.0f if pad_mask[b,n] else 1.0f
__device__ double   g_acc;              // global sum accumulator
__device__ unsigned g_cnt;              // blocks-done counter for last-block finalize

__device__ __forceinline__ float frcp_approx(float x) {
    float r;
    asm("rcp.approx.f32 %0, %1;" : "=f"(r) : "f"(x));
    return r;
}

// branchless: t in {0,1} -> returns r when t==1, +0.0f when t==0 (IMAD, no branch)
__device__ __forceinline__ float mask_mul(int t, float r) {
    return __int_as_float(t * __float_as_int(r));
}

// ---------------------------------------------------------------------------
// Kernel 1: locate the (unique) 1 per (b,n) channel WITHOUT branches.
// Exactly one element is 1, all others 0, so the flat index equals
//   sum_i [ 4*idx4_i*(vx+vy+vz+vw) + (vy + 2*vz + 3*vw) ]
// Pure IMAD/IADD inner loop (no BSSY/BSYNC), then a block sum-reduce.
// ---------------------------------------------------------------------------
__global__ __launch_bounds__(256) void k_centers(const int* __restrict__ tc,
                                                 const int* __restrict__ pad) {
    const int bn  = blockIdx.x;
    const int tid = threadIdx.x;
    if (bn == 0 && tid == 0) { g_acc = 0.0; g_cnt = 0u; }
    if (tid == 0) g_scale[bn] = pad[bn] ? 0.0f : 1.0f;

    const int4* p = reinterpret_cast<const int4*>(tc) + (size_t)bn * (HW / 4);
    int acc = 0;
    #pragma unroll 8
    for (int i = 0; i < 64; i++) {
        const int idx4 = i * 256 + tid;          // coalesced: warp reads 512B
        const int4 v = __ldcs(&p[idx4]);         // streaming: no reuse
        const int s  = (v.x + v.y) + (v.z + v.w);
        acc += (idx4 * 4) * s + (v.y + v.z * 2 + v.w * 3);
    }

    // block sum-reduce (exactly one thread saw the 1; everyone else adds 0)
    #pragma unroll
    for (int off = 16; off; off >>= 1)
        acc += __shfl_down_sync(0xffffffffu, acc, off);
    __shared__ int sred[8];
    if ((tid & 31) == 0) sred[tid >> 5] = acc;
    __syncthreads();
    if (tid < 8) {
        acc = sred[tid];
        acc += __shfl_down_sync(0xffu, acc, 4);
        acc += __shfl_down_sync(0xffu, acc, 2);
        acc += __shfl_down_sync(0xffu, acc, 1);
        if (tid == 0) g_cidx[bn] = acc;
    }
}

// ---------------------------------------------------------------------------
// Kernel 2: main fused pass + finalize.
// One block per (b,h) row; 256 threads = 4 n-partitions x 64 w-quads.
// Each thread: 4 consecutive w pixels (int4 loads) over 64 n values.
// Per-pixel denominator via single FMA (exact epsilon); pad folded into dr2
// as +INF (rcp.approx(INF)=+0); branchless integer-mask accumulate.
// minBlocksPerSM=5 -> <=51 regs -> 40 resident warps/SM.
// ---------------------------------------------------------------------------
__global__ __launch_bounds__(256, 5) void k_main(const float* __restrict__ pred,
                                                 const int*   __restrict__ tgt,
                                                 float*       __restrict__ out) {
    __shared__ float2 s_c [NN];      // (dr2eff, ccf)
    __shared__ float  s_imp[4][WW];  // per-partition importance partials
    __shared__ int    s_ts [4][WW];  // per-partition target-sum partials

    const int b   = blockIdx.x >> 8;   // grid = BB*HH = 1024
    const int h   = blockIdx.x & 255;
    const int tid = threadIdx.x;

    {
        const int n  = tid;
        const int ci = g_cidx[b * NN + n];
        const float dr = (float)(h - (ci >> 8));       // WW == 256
        float dr2 = dr * dr + 1e-6f;
        if (g_scale[b * NN + n] == 0.0f)
            dr2 = __int_as_float(0x7f800000);          // +INF -> rcp = +0
        s_c[n] = make_float2(dr2, (float)(ci & 255));
    }
    __syncthreads();

    const int q    = tid & 63;          // w-quad index
    const int part = tid >> 6;          // n partition 0..3
    const int w0   = q * 4;
    const float w0f = (float)w0;

    const int4* tp = reinterpret_cast<const int4*>(
                         tgt + (size_t)b * NN * HW + (size_t)h * WW)
                     + (size_t)part * 64 * (HW / 4) + q;
    const float2* cp = s_c + part * 64;

    float imp0 = 0.f, imp1 = 0.f, imp2 = 0.f, imp3 = 0.f;
    int   ts0 = 0, ts1 = 0, ts2 = 0, ts3 = 0;

    #pragma unroll 8
    for (int j = 0; j < 64; j++) {
        const int4 t = __ldcs(tp + (size_t)j * (HW / 4));  // 512B/warp, streaming
        const float2 c = cp[j];
        const float d0 = w0f - c.y;          // exact small integers in fp32
        const float d1 = d0 + 1.0f;
        const float d2 = d0 + 2.0f;
        const float d3 = d0 + 3.0f;

        imp0 += mask_mul(t.x, frcp_approx(fmaf(d0, d0, c.x))); ts0 += t.x;
        imp1 += mask_mul(t.y, frcp_approx(fmaf(d1, d1, c.x))); ts1 += t.y;
        imp2 += mask_mul(t.z, frcp_approx(fmaf(d2, d2, c.x))); ts2 += t.z;
        imp3 += mask_mul(t.w, frcp_approx(fmaf(d3, d3, c.x))); ts3 += t.w;
    }

    // vector stores of partials (16B-aligned: w0 = 4q)
    *reinterpret_cast<float4*>(&s_imp[part][w0]) = make_float4(imp0, imp1, imp2, imp3);
    *reinterpret_cast<int4*>  (&s_ts [part][w0]) = make_int4 (ts0, ts1, ts2, ts3);
    __syncthreads();

    // thread tid now owns pixel w = tid
    const int w = tid;
    const float imp = s_imp[0][w] + s_imp[1][w] + s_imp[2][w] + s_imp[3][w];
    const int   ts  = s_ts [0][w] + s_ts [1][w] + s_ts [2][w] + s_ts [3][w];

    // importance_coeff = ~tsum * 0.5  (bitwise invert: -ts-1)
    const float pi = imp + (float)(~ts) * 0.5f;

    const float x = pred[((size_t)b * HH + h) * WW + w];
    const float z = (float)ts;
    const float bce = fmaxf(x, 0.0f) - x * z + log1pf(expf(-fabsf(x)));

    double v = (double)(bce * pi);

    // warp reduce (double)
    #pragma unroll
    for (int off = 16; off; off >>= 1)
        v += __shfl_down_sync(0xffffffffu, v, off);

    __shared__ double s_red[8];
    const int lane = tid & 31;
    const int wid  = tid >> 5;
    if (lane == 0) s_red[wid] = v;
    __syncthreads();
    if (wid == 0) {
        v = (lane < 8) ? s_red[lane] : 0.0;
        #pragma unroll
        for (int off = 4; off; off >>= 1)
            v += __shfl_down_sync(0xffu, v, off);
        if (lane == 0) {
            atomicAdd(&g_acc, v);
            __threadfence();
            const unsigned done = atomicAdd(&g_cnt, 1u);
            if (done == (unsigned)gridDim.x - 1u) {
                const double total = atomicAdd(&g_acc, 0.0);  // coherent read
                out[0] = (float)(total * (1.0 / (double)(BB * HW)));
            }
        }
    }
}

// ---------------------------------------------------------------------------
// inputs (metadata order): predictions f32[4,256,256], target_centers i32[4,256,256,256],
//                          targets i32[4,256,256,256], pad_mask (bool->int32)[4,256]
// output: f32 scalar
// ---------------------------------------------------------------------------
extern "C" void kernel_launch(void* const* d_in, const int* in_sizes, int n_in,
                              void* d_out, int out_size) {
    const float* pred = (const float*)d_in[0];
    const int*   tc   = (const int*)d_in[1];
    const int*   tgt  = (const int*)d_in[2];
    const int*   pad  = (const int*)d_in[3];
    float* out = (float*)d_out;

    k_centers<<<BB * NN, 256>>>(tc, pad);
    k_main<<<BB * HH, 256>>>(pred, tgt, out);
}

// round 7
// speedup vs baseline: 1.0688x; 1.0688x over previous
#include <cuda_runtime.h>
#include <cuda_bf16.h>

#define BB 4
#define NN 256
#define HH 256
#define WW 256
#define HW 65536   // HH*WW

// Scratch (device globals — no allocations allowed)
__device__ int      g_cidx[BB * NN];    // flat center index within HxW for each (b,n)
__device__ float    g_scale[BB * NN];   // 0.0f if pad_mask[b,n] else 1.0f
__device__ double   g_acc;              // global sum accumulator
__device__ unsigned g_cnt;              // blocks-done counter for last-block finalize

__device__ __forceinline__ float frcp_approx(float x) {
    float r;
    asm("rcp.approx.f32 %0, %1;" : "=f"(r) : "f"(x));
    return r;
}

// branchless: t in {0,1} -> returns r when t==1, +0.0f when t==0 (IMAD, no branch)
__device__ __forceinline__ float mask_mul(int t, float r) {
    return __int_as_float(t * __float_as_int(r));
}

// ---------------------------------------------------------------------------
// Kernel 1: locate the (unique) 1 per (b,n) channel WITHOUT branches.
// Exactly one element is 1, all others 0, so the flat index equals
//   sum_i [ 4*idx4_i*(vx+vy+vz+vw) + (vy + 2*vz + 3*vw) ]
// Pure IMAD/IADD inner loop (no BSSY/BSYNC), then a block sum-reduce.
// (R6-measured ~38us, ~7.0 TB/s — at the LTS ceiling.)
// ---------------------------------------------------------------------------
__global__ __launch_bounds__(256) void k_centers(const int* __restrict__ tc,
                                                 const int* __restrict__ pad) {
    const int bn  = blockIdx.x;
    const int tid = threadIdx.x;
    if (bn == 0 && tid == 0) { g_acc = 0.0; g_cnt = 0u; }
    if (tid == 0) g_scale[bn] = pad[bn] ? 0.0f : 1.0f;

    const int4* p = reinterpret_cast<const int4*>(tc) + (size_t)bn * (HW / 4);
    int acc = 0;
    #pragma unroll 8
    for (int i = 0; i < 64; i++) {
        const int idx4 = i * 256 + tid;          // coalesced: warp reads 512B
        const int4 v = __ldcs(&p[idx4]);         // streaming: no reuse
        const int s  = (v.x + v.y) + (v.z + v.w);
        acc += (idx4 * 4) * s + (v.y + v.z * 2 + v.w * 3);
    }

    // block sum-reduce (exactly one thread saw the 1; everyone else adds 0)
    #pragma unroll
    for (int off = 16; off; off >>= 1)
        acc += __shfl_down_sync(0xffffffffu, acc, off);
    __shared__ int sred[8];
    if ((tid & 31) == 0) sred[tid >> 5] = acc;
    __syncthreads();
    if (tid < 8) {
        acc = sred[tid];
        acc += __shfl_down_sync(0xffu, acc, 4);
        acc += __shfl_down_sync(0xffu, acc, 2);
        acc += __shfl_down_sync(0xffu, acc, 1);
        if (tid == 0) g_cidx[bn] = acc;
    }
}

// ---------------------------------------------------------------------------
// Kernel 2: main fused pass + finalize. (Exact R5 configuration — measured
// 50.1us; the R6 launch_bounds(256,5) register squeeze regressed it.)
// One block per (b,h) row; 256 threads = 4 n-partitions x 64 w-quads.
// Each thread: 4 consecutive w pixels (int4 loads) over 64 n values.
// Per-pixel denominator via single FMA (exact epsilon); pad folded into dr2
// as +INF (rcp.approx(INF)=+0); branchless integer-mask accumulate.
// ---------------------------------------------------------------------------
__global__ __launch_bounds__(256) void k_main(const float* __restrict__ pred,
                                              const int*   __restrict__ tgt,
                                              float*       __restrict__ out) {
    __shared__ float2 s_c [NN];      // (dr2eff, ccf)
    __shared__ float  s_imp[4][WW];  // per-partition importance partials
    __shared__ int    s_ts [4][WW];  // per-partition target-sum partials

    const int b   = blockIdx.x >> 8;   // grid = BB*HH = 1024
    const int h   = blockIdx.x & 255;
    const int tid = threadIdx.x;

    {
        const int n  = tid;
        const int ci = g_cidx[b * NN + n];
        const float dr = (float)(h - (ci >> 8));       // WW == 256
        float dr2 = dr * dr + 1e-6f;
        if (g_scale[b * NN + n] == 0.0f)
            dr2 = __int_as_float(0x7f800000);          // +INF -> rcp = +0
        s_c[n] = make_float2(dr2, (float)(ci & 255));
    }
    __syncthreads();

    const int q    = tid & 63;          // w-quad index
    const int part = tid >> 6;          // n partition 0..3
    const int w0   = q * 4;
    const float w0f = (float)w0;

    const int4* tp = reinterpret_cast<const int4*>(
                         tgt + (size_t)b * NN * HW + (size_t)h * WW)
                     + (size_t)part * 64 * (HW / 4) + q;

    float imp0 = 0.f, imp1 = 0.f, imp2 = 0.f, imp3 = 0.f;
    int   ts0 = 0, ts1 = 0, ts2 = 0, ts3 = 0;

    #pragma unroll 8
    for (int j = 0; j < 64; j++) {
        const int4 t = __ldcs(tp + (size_t)j * (HW / 4));  // 512B/warp, streaming
        const float2 c = s_c[part * 64 + j];
        const float d0 = w0f - c.y;          // exact small integers in fp32
        const float d1 = d0 + 1.0f;
        const float d2 = d0 + 2.0f;
        const float d3 = d0 + 3.0f;

        imp0 += mask_mul(t.x, frcp_approx(fmaf(d0, d0, c.x))); ts0 += t.x;
        imp1 += mask_mul(t.y, frcp_approx(fmaf(d1, d1, c.x))); ts1 += t.y;
        imp2 += mask_mul(t.z, frcp_approx(fmaf(d2, d2, c.x))); ts2 += t.z;
        imp3 += mask_mul(t.w, frcp_approx(fmaf(d3, d3, c.x))); ts3 += t.w;
    }

    // vector stores of partials (16B-aligned: w0 = 4q)
    *reinterpret_cast<float4*>(&s_imp[part][w0]) = make_float4(imp0, imp1, imp2, imp3);
    *reinterpret_cast<int4*>  (&s_ts [part][w0]) = make_int4 (ts0, ts1, ts2, ts3);
    __syncthreads();

    // thread tid now owns pixel w = tid
    const int w = tid;
    const float imp = s_imp[0][w] + s_imp[1][w] + s_imp[2][w] + s_imp[3][w];
    const int   ts  = s_ts [0][w] + s_ts [1][w] + s_ts [2][w] + s_ts [3][w];

    // importance_coeff = ~tsum * 0.5  (bitwise invert: -ts-1)
    const float pi = imp + (float)(~ts) * 0.5f;

    const float x = pred[((size_t)b * HH + h) * WW + w];
    const float z = (float)ts;
    const float bce = fmaxf(x, 0.0f) - x * z + log1pf(expf(-fabsf(x)));

    double v = (double)(bce * pi);

    // warp reduce (double)
    #pragma unroll
    for (int off = 16; off; off >>= 1)
        v += __shfl_down_sync(0xffffffffu, v, off);

    __shared__ double s_red[8];
    const int lane = tid & 31;
    const int wid  = tid >> 5;
    if (lane == 0) s_red[wid] = v;
    __syncthreads();
    if (wid == 0) {
        v = (lane < 8) ? s_red[lane] : 0.0;
        #pragma unroll
        for (int off = 4; off; off >>= 1)
            v += __shfl_down_sync(0xffu, v, off);
        if (lane == 0) {
            atomicAdd(&g_acc, v);
            __threadfence();
            const unsigned done = atomicAdd(&g_cnt, 1u);
            if (done == (unsigned)gridDim.x - 1u) {
                const double total = atomicAdd(&g_acc, 0.0);  // coherent read
                out[0] = (float)(total * (1.0 / (double)(BB * HW)));
            }
        }
    }
}

// ---------------------------------------------------------------------------
// inputs (metadata order): predictions f32[4,256,256], target_centers i32[4,256,256,256],
//                          targets i32[4,256,256,256], pad_mask (bool->int32)[4,256]
// output: f32 scalar
// ---------------------------------------------------------------------------
extern "C" void kernel_launch(void* const* d_in, const int* in_sizes, int n_in,
                              void* d_out, int out_size) {
    const float* pred = (const float*)d_in[0];
    const int*   tc   = (const int*)d_in[1];
    const int*   tgt  = (const int*)d_in[2];
    const int*   pad  = (const int*)d_in[3];
    float* out = (float*)d_out;

    k_centers<<<BB * NN, 256>>>(tc, pad);
    k_main<<<BB * HH, 256>>>(pred, tgt, out);
}

// round 8
// speedup vs baseline: 1.1303x; 1.0575x over previous
#include <cuda_runtime.h>
#include <cuda_bf16.h>

#define BB 4
#define NN 256
#define HH 256
#define WW 256
#define HW 65536   // HH*WW

// Scratch (device globals — no allocations allowed)
__device__ int      g_cidx[BB * NN];    // flat center index within HxW for each (b,n)
__device__ float    g_scale[BB * NN];   // 0.0f if pad_mask[b,n] else 1.0f
__device__ double   g_acc;              // global sum accumulator
__device__ unsigned g_cnt;              // blocks-done counter for last-block finalize

__device__ __forceinline__ float frcp_approx(float x) {
    float r;
    asm("rcp.approx.f32 %0, %1;" : "=f"(r) : "f"(x));
    return r;
}

// branchless: t in {0,1} -> returns r when t==1, +0.0f when t==0 (IMAD, no branch)
__device__ __forceinline__ float mask_mul(int t, float r) {
    return __int_as_float(t * __float_as_int(r));
}

// ---------------------------------------------------------------------------
// Kernel 1: locate the (unique) 1 per (b,n) channel WITHOUT branches.
// (Pinned R6 config — measured ~38us, ~7.0 TB/s, at the LTS ceiling.)
// ---------------------------------------------------------------------------
__global__ __launch_bounds__(256) void k_centers(const int* __restrict__ tc,
                                                 const int* __restrict__ pad) {
    const int bn  = blockIdx.x;
    const int tid = threadIdx.x;
    if (bn == 0 && tid == 0) { g_acc = 0.0; g_cnt = 0u; }
    if (tid == 0) g_scale[bn] = pad[bn] ? 0.0f : 1.0f;

    const int4* p = reinterpret_cast<const int4*>(tc) + (size_t)bn * (HW / 4);
    int acc = 0;
    #pragma unroll 8
    for (int i = 0; i < 64; i++) {
        const int idx4 = i * 256 + tid;          // coalesced: warp reads 512B
        const int4 v = __ldcs(&p[idx4]);         // streaming: no reuse
        const int s  = (v.x + v.y) + (v.z + v.w);
        acc += (idx4 * 4) * s + (v.y + v.z * 2 + v.w * 3);
    }

    #pragma unroll
    for (int off = 16; off; off >>= 1)
        acc += __shfl_down_sync(0xffffffffu, acc, off);
    __shared__ int sred[8];
    if ((tid & 31) == 0) sred[tid >> 5] = acc;
    __syncthreads();
    if (tid < 8) {
        acc = sred[tid];
        acc += __shfl_down_sync(0xffu, acc, 4);
        acc += __shfl_down_sync(0xffu, acc, 2);
        acc += __shfl_down_sync(0xffu, acc, 1);
        if (tid == 0) g_cidx[bn] = acc;
    }
}

// ---------------------------------------------------------------------------
// Kernel 2: main fused pass + finalize — SINGLE-WAVE layout.
// grid = 1024 (one per (b,h) row), block = 128 threads, 7 CTAs/SM resident
// -> all 1024 CTAs in one wave (no 73%-full second wave).
// 4 warps = 4 n-partitions (64 n each); each thread owns 8 pixels:
// quad0 at w=4*lane, quad1 at w=4*lane+128 (two independent int4 loads/iter).
// ts counts byte-packed (max 64 per partition) to stay under the 73-reg cap.
// ---------------------------------------------------------------------------
__global__ __launch_bounds__(128, 7) void k_main(const float* __restrict__ pred,
                                                 const int*   __restrict__ tgt,
                                                 float*       __restrict__ out) {
    __shared__ float2 s_c [NN];      // (dr2eff, ccf)
    __shared__ float  s_imp[4][WW];  // per-partition importance partials
    __shared__ int    s_ts [4][WW];  // per-partition target-sum partials

    const int b   = blockIdx.x >> 8;   // grid = BB*HH = 1024
    const int h   = blockIdx.x & 255;
    const int tid = threadIdx.x;

    #pragma unroll
    for (int k = 0; k < 2; k++) {
        const int n  = tid + k * 128;
        const int ci = g_cidx[b * NN + n];
        const float dr = (float)(h - (ci >> 8));       // WW == 256
        float dr2 = dr * dr + 1e-6f;
        if (g_scale[b * NN + n] == 0.0f)
            dr2 = __int_as_float(0x7f800000);          // +INF -> rcp = +0
        s_c[n] = make_float2(dr2, (float)(ci & 255));
    }
    __syncthreads();

    const int lane = tid & 31;
    const int part = tid >> 5;          // warp = n-partition 0..3
    const float w0f = (float)(lane * 4);

    const int4* tp0 = reinterpret_cast<const int4*>(
                          tgt + (size_t)b * NN * HW + (size_t)h * WW)
                      + (size_t)part * 64 * (HW / 4) + lane;
    const int4* tp1 = tp0 + 32;
    const float2* cp = s_c + part * 64;

    float impA0 = 0.f, impA1 = 0.f, impA2 = 0.f, impA3 = 0.f;   // quad0
    float impB0 = 0.f, impB1 = 0.f, impB2 = 0.f, impB3 = 0.f;   // quad1
    int   tspA = 0, tspB = 0;                                    // byte-packed counts

    #pragma unroll 4
    for (int j = 0; j < 64; j++) {
        const int4 t0 = __ldcs(tp0 + (size_t)j * (HW / 4));   // independent
        const int4 t1 = __ldcs(tp1 + (size_t)j * (HW / 4));   // independent
        const float2 c = cp[j];
        const float d0 = w0f - c.y;           // exact small integers in fp32
        const float d1 = d0 + 1.0f;
        const float d2 = d0 + 2.0f;
        const float d3 = d0 + 3.0f;
        const float e0 = d0 + 128.0f;
        const float e1 = d0 + 129.0f;
        const float e2 = d0 + 130.0f;
        const float e3 = d0 + 131.0f;

        impA0 += mask_mul(t0.x, frcp_approx(fmaf(d0, d0, c.x)));
        impA1 += mask_mul(t0.y, frcp_approx(fmaf(d1, d1, c.x)));
        impA2 += mask_mul(t0.z, frcp_approx(fmaf(d2, d2, c.x)));
        impA3 += mask_mul(t0.w, frcp_approx(fmaf(d3, d3, c.x)));
        impB0 += mask_mul(t1.x, frcp_approx(fmaf(e0, e0, c.x)));
        impB1 += mask_mul(t1.y, frcp_approx(fmaf(e1, e1, c.x)));
        impB2 += mask_mul(t1.z, frcp_approx(fmaf(e2, e2, c.x)));
        impB3 += mask_mul(t1.w, frcp_approx(fmaf(e3, e3, c.x)));

        tspA += t0.x + t0.y * 256 + t0.z * 65536 + t0.w * 16777216;
        tspB += t1.x + t1.y * 256 + t1.z * 65536 + t1.w * 16777216;
    }

    // vector stores of partials (16B-aligned)
    const int w0 = lane * 4;
    *reinterpret_cast<float4*>(&s_imp[part][w0])       = make_float4(impA0, impA1, impA2, impA3);
    *reinterpret_cast<float4*>(&s_imp[part][w0 + 128]) = make_float4(impB0, impB1, impB2, impB3);
    *reinterpret_cast<int4*>  (&s_ts [part][w0])       =
        make_int4(tspA & 255, (tspA >> 8) & 255, (tspA >> 16) & 255, (tspA >> 24) & 255);
    *reinterpret_cast<int4*>  (&s_ts [part][w0 + 128]) =
        make_int4(tspB & 255, (tspB >> 8) & 255, (tspB >> 16) & 255, (tspB >> 24) & 255);
    __syncthreads();

    // each thread finalizes 2 pixels: w = tid and w = tid + 128
    double v = 0.0;
    #pragma unroll
    for (int k = 0; k < 2; k++) {
        const int w = tid + k * 128;
        const float imp = s_imp[0][w] + s_imp[1][w] + s_imp[2][w] + s_imp[3][w];
        const int   ts  = s_ts [0][w] + s_ts [1][w] + s_ts [2][w] + s_ts [3][w];

        // importance_coeff = ~tsum * 0.5  (bitwise invert: -ts-1)
        const float pi = imp + (float)(~ts) * 0.5f;

        const float x = pred[((size_t)b * HH + h) * WW + w];
        const float z = (float)ts;
        const float bce = fmaxf(x, 0.0f) - x * z + log1pf(expf(-fabsf(x)));
        v += (double)(bce * pi);
    }

    // warp reduce (double)
    #pragma unroll
    for (int off = 16; off; off >>= 1)
        v += __shfl_down_sync(0xffffffffu, v, off);

    __shared__ double s_red[4];
    if (lane == 0) s_red[part] = v;
    __syncthreads();
    if (tid < 4) {
        v = s_red[tid];
        v += __shfl_down_sync(0xfu, v, 2);
        v += __shfl_down_sync(0xfu, v, 1);
        if (tid == 0) {
            atomicAdd(&g_acc, v);
            __threadfence();
            const unsigned done = atomicAdd(&g_cnt, 1u);
            if (done == (unsigned)gridDim.x - 1u) {
                const double total = atomicAdd(&g_acc, 0.0);  // coherent read
                out[0] = (float)(total * (1.0 / (double)(BB * HW)));
            }
        }
    }
}

// ---------------------------------------------------------------------------
// inputs (metadata order): predictions f32[4,256,256], target_centers i32[4,256,256,256],
//                          targets i32[4,256,256,256], pad_mask (bool->int32)[4,256]
// output: f32 scalar
// ---------------------------------------------------------------------------
extern "C" void kernel_launch(void* const* d_in, const int* in_sizes, int n_in,
                              void* d_out, int out_size) {
    const float* pred = (const float*)d_in[0];
    const int*   tc   = (const int*)d_in[1];
    const int*   tgt  = (const int*)d_in[2];
    const int*   pad  = (const int*)d_in[3];
    float* out = (float*)d_out;

    k_centers<<<BB * NN, 256>>>(tc, pad);
    k_main<<<BB * HH, 128>>>(pred, tgt, out);
}